// round 12
// baseline (speedup 1.0000x reference)
#include <cuda_runtime.h>
#include <math.h>

// ---------------------------------------------------------------------------
// CNN-LSTM: emb-gather -> conv1d(K=5,VALID) -> relu -> maxpool(4) -> LSTM -> FC
// B=64 L=4096 VOCAB=20000 E=128 F=64 K=5 P=4 H=128 C=2
//
//   K0: transpose conv_w -> [e][k*64+f]
//   K1: proj[v][k][f] = emb[v] . conv_w[f,:,k]   (20000x320 table, L2-resident)
//   K2: conv+relu+pool via 20 L2-hit gathers per pooled output
//   K3: xg = pooled @ w_ih^T + biases   (1 col x 8 rows/thread, 2 CTAs/SM)
//   K4: persistent LSTM, 1 CTA/batch, shuffle-paired gates, ONE barrier/step,
//       4 accumulator chains, 2-step xg prefetch
// ---------------------------------------------------------------------------

using u64 = unsigned long long;
#define DI __device__ __forceinline__

namespace {
constexpr int B_ = 64, L_ = 4096, E_ = 128, F_ = 64, K_ = 5, H_ = 128;
constexpr int VOCAB_ = 20000;
constexpr int FK_ = K_ * F_;     // 320
constexpr int LP_ = 1023;        // pooled sequence length (4092/4)
constexpr int G_ = 4 * H_;       // 512 gate rows
constexpr int M_ = B_ * LP_;     // 65472 pooled rows
}

// scratch (device globals -- no runtime allocation allowed)
__device__ float g_cwt[E_ * FK_];        // transposed conv weights
__device__ float g_proj[VOCAB_ * FK_];   // 25.6 MB token->conv projection table
__device__ float g_pooled[M_ * F_];      // 16.8 MB pooled features
__device__ float g_xg[M_ * G_];          // 134 MB precomputed gate inputs

// ---- packed f32x2 helpers (Blackwell FFMA2) -------------------------------
DI void fma2(u64 &acc, u64 a, u64 b) {
    asm("fma.rn.f32x2 %0, %1, %2, %0;" : "+l"(acc) : "l"(a), "l"(b));
}
DI u64 pk2(float lo, float hi) {
    u64 r;
    asm("mov.b64 %0, {%1, %2};" : "=l"(r) : "f"(lo), "f"(hi));
    return r;
}
DI float sum2(u64 v) {
    float lo, hi;
    asm("mov.b64 {%0, %1}, %2;" : "=f"(lo), "=f"(hi) : "l"(v));
    return lo + hi;
}

DI float sigf(float x) { return 1.0f / (1.0f + __expf(-x)); }

// ---- K0: transpose conv_w [F,E,K] -> g_cwt[e][k*64+f] ---------------------
__global__ void k_wt(const float* __restrict__ cw) {
    int i = blockIdx.x * 256 + threadIdx.x;
    if (i < E_ * FK_) {
        int e = i / FK_, col = i % FK_;
        int k = col >> 6, f = col & 63;
        g_cwt[i] = cw[(f * E_ + e) * K_ + k];
    }
}

// ---- K1: proj table GEMM. CTA = 32 vocab rows staged in smem --------------
__global__ void __launch_bounds__(320) k_proj(const float* __restrict__ emb) {
    __shared__ __align__(16) float es[32 * E_];   // 16 KB
    int c = threadIdx.x;
    u64 w[64];
#pragma unroll
    for (int j = 0; j < 64; j++)
        w[j] = pk2(g_cwt[(2 * j) * FK_ + c], g_cwt[(2 * j + 1) * FK_ + c]);
    int v0 = blockIdx.x * 32;
    const float4* src = (const float4*)(emb + v0 * E_);
    for (int i = threadIdx.x; i < 32 * E_ / 4; i += 320)
        ((float4*)es)[i] = src[i];
    __syncthreads();
#pragma unroll 1
    for (int vi = 0; vi < 32; vi++) {
        const ulonglong2* h4 = (const ulonglong2*)(es + vi * E_);
        u64 a0 = 0ull, a1 = 0ull;
#pragma unroll
        for (int j = 0; j < 32; j++) {
            ulonglong2 h = h4[j];
            fma2(a0, h.x, w[2 * j]);
            fma2(a1, h.y, w[2 * j + 1]);
        }
        g_proj[(v0 + vi) * FK_ + c] = sum2(a0) + sum2(a1);
    }
}

// ---- K2: conv + relu + maxpool. thread = (b, pooled pos p, feature f) -----
__global__ void k_convpool(const int* __restrict__ x, const float* __restrict__ cb) {
    int f = threadIdx.x & 63;
    int p = blockIdx.x * 4 + (threadIdx.x >> 6);
    int b = blockIdx.y;
    if (p >= LP_) return;
    const int* xb = x + b * L_;
    int s0 = p * 4;
    int tok[8];
#pragma unroll
    for (int i = 0; i < 8; i++) tok[i] = __ldg(xb + s0 + i);
    float a0 = 0.f, a1 = 0.f, a2 = 0.f, a3 = 0.f;
#pragma unroll
    for (int k = 0; k < K_; k++) {
        const float* pr = g_proj + k * 64 + f;
        a0 += __ldg(pr + tok[k + 0] * FK_);
        a1 += __ldg(pr + tok[k + 1] * FK_);
        a2 += __ldg(pr + tok[k + 2] * FK_);
        a3 += __ldg(pr + tok[k + 3] * FK_);
    }
    float bias = __ldg(cb + f);
    float m = fmaxf(fmaxf(a0, a1), fmaxf(a2, a3)) + bias;
    g_pooled[(b * LP_ + p) * F_ + f] = fmaxf(m, 0.0f);  // relu(max) == max(relu)
}

// ---- K3: xg = pooled @ w_ih^T + (b_ih + b_hh) ------------------------------
// CTA = 256 threads = 256 gate cols (gridDim.y picks col half), 64 pooled rows
// staged in smem, 8-row register blocking -> 8 independent acc chains.
// <=128 regs (launch_bounds ,2) so 2 CTAs/SM: 16 warps to hide LDS latency.
__global__ void __launch_bounds__(256, 2) k_xgate(const float* __restrict__ wih,
                                                  const float* __restrict__ bih,
                                                  const float* __restrict__ bhh) {
    __shared__ __align__(16) float ps[64 * F_];   // 16 KB
    int t = threadIdx.x;
    int g = blockIdx.y * 256 + t;
    u64 w[32];
    const u64* wr = (const u64*)(wih + g * F_);
#pragma unroll
    for (int j = 0; j < 32; j++) w[j] = wr[j];
    float bias = __ldg(bih + g) + __ldg(bhh + g);
    int row0 = blockIdx.x * 64;
    const float4* src = (const float4*)(g_pooled + row0 * F_);
#pragma unroll
    for (int i = 0; i < 4; i++) ((float4*)ps)[t + i * 256] = src[t + i * 256];
    __syncthreads();
#pragma unroll 1
    for (int r = 0; r < 64; r += 8) {
        u64 a[8];
#pragma unroll
        for (int q = 0; q < 8; q++) a[q] = 0ull;
#pragma unroll
        for (int j = 0; j < 16; j++) {
            u64 wl = w[2 * j], wh = w[2 * j + 1];
#pragma unroll
            for (int q = 0; q < 8; q++) {
                ulonglong2 h = *((const ulonglong2*)(ps + (r + q) * F_) + j);
                fma2(a[q], h.x, wl);
                fma2(a[q], h.y, wh);
            }
        }
        float* dst = g_xg + (size_t)(row0 + r) * G_ + g;
#pragma unroll
        for (int q = 0; q < 8; q++) dst[(size_t)q * G_] = sum2(a[q]) + bias;
    }
}

// ---- K4: persistent LSTM. 1 CTA/batch, 256 threads, 2 gate rows/thread ----
// Warp w, lane l. Element e = w*16 + (l&15). Lanes 0-15 ("role A") own gate
// rows (i=e, g=256+e) and the cell state c[e]; lanes 16-31 ("role B") own
// rows (f=128+e, o=384+e). f/o activations hop A<-B via __shfl_down(16),
// so each step needs only ONE __syncthreads (publish h).
// Weights: rowA in regs (64 u64), rowB 32 u64 regs + 16 ulonglong2 smem.
// 4 accumulator chains (32-deep each); xg prefetched 2 steps ahead.
__global__ void __launch_bounds__(256, 1) k_lstm(const float* __restrict__ whh,
                                                 const float* __restrict__ fcw,
                                                 const float* __restrict__ fcb,
                                                 float* __restrict__ out) {
    extern __shared__ float sm[];
    ulonglong2* wsm = (ulonglong2*)sm;    // [16][256] ulonglong2 -> 64 KB
    float* hs = sm + 16384;               // [128] hidden state (16B aligned)
    int t = threadIdx.x;
    int b = blockIdx.x;
    int l = t & 31;
    bool roleA = (l < 16);
    int e = (t >> 5) * 16 + (l & 15);
    int rowA = roleA ? e : (128 + e);          // i : f
    int rowB = roleA ? (256 + e) : (384 + e);  // g : o

    u64 wa[64], wb[32];
    const u64* rA = (const u64*)(whh + rowA * H_);
    const u64* rB = (const u64*)(whh + rowB * H_);
#pragma unroll
    for (int j = 0; j < 64; j++) wa[j] = rA[j];
#pragma unroll
    for (int j = 0; j < 32; j++) wb[j] = rB[j];
    const ulonglong2* rB2 = (const ulonglong2*)(whh + rowB * H_ + 64);
#pragma unroll
    for (int p2 = 0; p2 < 16; p2++) wsm[p2 * 256 + t] = rB2[p2];
    if (t < 128) hs[t] = 0.0f;
    float c = 0.0f;
    __syncthreads();

    const float* xgb = g_xg + (size_t)b * (LP_ * G_);
    // 2-deep xg prefetch ring (covers DRAM latency even on fast steps)
    float xa0  = __ldg(xgb + rowA);
    float xb0  = __ldg(xgb + rowB);
    float xa1  = __ldg(xgb + G_ + rowA);
    float xb1  = __ldg(xgb + G_ + rowB);
#pragma unroll 1
    for (int p = 0; p < LP_; p++) {
        int pn = (p + 2 < LP_) ? p + 2 : LP_ - 1;
        float xa2 = __ldg(xgb + (size_t)pn * G_ + rowA);
        float xb2n = __ldg(xgb + (size_t)pn * G_ + rowB);

        const ulonglong2* h4 = (const ulonglong2*)hs;
        u64 aA0 = 0ull, aA1 = 0ull, aB0 = 0ull, aB1 = 0ull;
#pragma unroll
        for (int j = 0; j < 16; j += 2) {     // h[0:64): both operands in regs
            ulonglong2 h0 = h4[j], h1 = h4[j + 1];
            fma2(aA0, h0.x, wa[2 * j]);     fma2(aA0, h0.y, wa[2 * j + 1]);
            fma2(aA1, h1.x, wa[2 * j + 2]); fma2(aA1, h1.y, wa[2 * j + 3]);
            fma2(aB0, h0.x, wb[2 * j]);     fma2(aB0, h0.y, wb[2 * j + 1]);
            fma2(aB1, h1.x, wb[2 * j + 2]); fma2(aB1, h1.y, wb[2 * j + 3]);
        }
#pragma unroll
        for (int j = 16; j < 32; j += 2) {    // h[64:128): rowB weights from smem
            ulonglong2 h0 = h4[j], h1 = h4[j + 1];
            ulonglong2 wv0 = wsm[(j - 16) * 256 + t];
            ulonglong2 wv1 = wsm[(j - 15) * 256 + t];
            fma2(aA0, h0.x, wa[2 * j]);     fma2(aA0, h0.y, wa[2 * j + 1]);
            fma2(aA1, h1.x, wa[2 * j + 2]); fma2(aA1, h1.y, wa[2 * j + 3]);
            fma2(aB0, h0.x, wv0.x);         fma2(aB0, h0.y, wv0.y);
            fma2(aB1, h1.x, wv1.x);         fma2(aB1, h1.y, wv1.y);
        }
        float pA = sum2(aA0) + sum2(aA1) + xa0;   // i-pre (A) / f-pre (B)
        float pB = sum2(aB0) + sum2(aB1) + xb0;   // g-pre (A) / o-pre (B)
        xa0 = xa1; xb0 = xb1; xa1 = xa2; xb1 = xb2n;

        float sA = sigf(pA);                       // ii (A) / ff (B)
        float q  = roleA ? (pB + pB) : pB;         // tanh(x)=2*sig(2x)-1
        float sq = sigf(q);
        float vB = roleA ? (2.0f * sq - 1.0f) : sq;  // tg (A) / oo (B)

        float ff = __shfl_down_sync(0xffffffffu, sA, 16);
        float oo = __shfl_down_sync(0xffffffffu, vB, 16);
        if (roleA) {
            c = ff * c + sA * vB;
            float tc = 2.0f * sigf(c + c) - 1.0f;  // tanh(c)
            hs[e] = oo * tc;
        }
        __syncthreads();
    }

    // final FC: out[b][cc] = h . fc_w[cc] + fc_b[cc]
    if (t < 64) {
        int cc = t >> 5, lane = t & 31;
        float s = 0.0f;
#pragma unroll
        for (int u = 0; u < 4; u++)
            s += hs[lane + u * 32] * __ldg(fcw + cc * H_ + lane + u * 32);
#pragma unroll
        for (int off = 16; off; off >>= 1) s += __shfl_down_sync(0xffffffffu, s, off);
        if (lane == 0) out[b * 2 + cc] = s + __ldg(fcb + cc);
    }
}

// ---------------------------------------------------------------------------
extern "C" void kernel_launch(void* const* d_in, const int* in_sizes, int n_in,
                              void* d_out, int out_size) {
    const int*   x   = (const int*)d_in[0];
    const float* emb = (const float*)d_in[1];
    const float* cw  = (const float*)d_in[2];
    const float* cb  = (const float*)d_in[3];
    const float* wih = (const float*)d_in[4];
    const float* whh = (const float*)d_in[5];
    const float* bih = (const float*)d_in[6];
    const float* bhh = (const float*)d_in[7];
    const float* fcw = (const float*)d_in[8];
    const float* fcb = (const float*)d_in[9];
    float* out = (float*)d_out;

    const int lstm_smem = (16384 + 128) * 4;  // 66048 B dynamic smem
    cudaFuncSetAttribute(k_lstm, cudaFuncAttributeMaxDynamicSharedMemorySize,
                         lstm_smem);

    k_wt<<<(E_ * FK_ + 255) / 256, 256>>>(cw);
    k_proj<<<VOCAB_ / 32, 320>>>(emb);
    k_convpool<<<dim3((LP_ + 3) / 4, B_), 256>>>(x, cb);
    k_xgate<<<dim3(M_ / 64, 2), 256>>>(wih, bih, bhh);
    k_lstm<<<B_, 256, lstm_smem>>>(whh, fcw, fcb, out);
}